// round 14
// baseline (speedup 1.0000x reference)
#include <cuda_runtime.h>
#include <cuda_bf16.h>
#include <cuda_fp16.h>
#include <cstdint>

// Problem constants (fixed shapes)
#define N_TOK 8192     // D*H*W
#define BATCH 2
#define CC 96
#define CV 288
#define KIN 320

// ---------------------------------------------------------------------------
// Device scratch
// ---------------------------------------------------------------------------
__device__ float g_W64[CC * CV];     // W6 @ W4  (fp32, stage-A scratch)
__device__ float g_bvc[CV];          // combined v bias (fp32, stage-A scratch)

__device__ __align__(128) __nv_bfloat16 g_Wkv[2 * CC * KIN]; // rows 0-95: Wks(log2e), 96-191: Wv6
__device__ float         g_bks[CC];
__device__ float         g_bv6[CC];
__device__ __align__(128) __nv_bfloat16 g_Wq[CC * CC];
__device__ __align__(128) __nv_bfloat16 g_ksum[(size_t)BATCH * N_TOK * CC];  // [B,N,96] bf16 (log2e)
__device__ __align__(128) __nv_bfloat16 g_q[(size_t)BATCH * N_TOK * CC];     // [B,N,96] bf16
__device__ __align__(128) __half        g_v6[(size_t)BATCH * CC * N_TOK];    // [B,96,N] fp16

// ---------------------------------------------------------------------------
// Helpers
// ---------------------------------------------------------------------------
__device__ __forceinline__ uint32_t ld32bf(const __nv_bfloat16* p) {
    return *reinterpret_cast<const uint32_t*>(p);
}

__device__ __forceinline__ void mma_bf16(float& d0, float& d1, float& d2, float& d3,
                                         uint32_t a0, uint32_t a1, uint32_t a2, uint32_t a3,
                                         uint32_t b0, uint32_t b1)
{
    asm volatile(
        "mma.sync.aligned.m16n8k16.row.col.f32.bf16.bf16.f32 "
        "{%0,%1,%2,%3}, {%4,%5,%6,%7}, {%8,%9}, {%0,%1,%2,%3};\n"
        : "+f"(d0), "+f"(d1), "+f"(d2), "+f"(d3)
        : "r"(a0), "r"(a1), "r"(a2), "r"(a3), "r"(b0), "r"(b1));
}

__device__ __forceinline__ void mma_f16(float& d0, float& d1, float& d2, float& d3,
                                        uint32_t a0, uint32_t a1, uint32_t a2, uint32_t a3,
                                        uint32_t b0, uint32_t b1)
{
    asm volatile(
        "mma.sync.aligned.m16n8k16.row.col.f32.f16.f16.f32 "
        "{%0,%1,%2,%3}, {%4,%5,%6,%7}, {%8,%9}, {%0,%1,%2,%3};\n"
        : "+f"(d0), "+f"(d1), "+f"(d2), "+f"(d3)
        : "r"(a0), "r"(a1), "r"(a2), "r"(a3), "r"(b0), "r"(b1));
}

__device__ __forceinline__ void ldsm4(uint32_t addr, uint32_t& r0, uint32_t& r1,
                                      uint32_t& r2, uint32_t& r3)
{
    asm volatile("ldmatrix.sync.aligned.m8n8.x4.shared.b16 {%0,%1,%2,%3}, [%4];\n"
                 : "=r"(r0), "=r"(r1), "=r"(r2), "=r"(r3) : "r"(addr));
}

__device__ __forceinline__ void cp16(uint32_t smem_dst, const void* gsrc)
{
    asm volatile("cp.async.cg.shared.global [%0], [%1], 16;\n"
                 :: "r"(smem_dst), "l"(gsrc));
}
__device__ __forceinline__ void cp_commit() { asm volatile("cp.async.commit_group;\n"); }
__device__ __forceinline__ void cp_wait0()  { asm volatile("cp.async.wait_group 0;\n"); }

__device__ __forceinline__ void sts32(uint32_t addr, uint32_t v)
{
    asm volatile("st.shared.b32 [%0], %1;" :: "r"(addr), "r"(v) : "memory");
}

__device__ __forceinline__ void bar_pair(int id)
{
    asm volatile("bar.sync %0, 64;" :: "r"(id) : "memory");
}

// exp2 on two packed fp16; inputs fp32 (log2 domain), output f16x2 bits
__device__ __forceinline__ uint32_t ex2_f16x2(float a, float b)
{
    __half2 h = __floats2half2_rn(a, b);
    uint32_t hin = *reinterpret_cast<uint32_t*>(&h);
    uint32_t r;
    asm("ex2.approx.f16x2 %0, %1;" : "=r"(r) : "r"(hin));
    return r;
}

// ---------------------------------------------------------------------------
// Prep stage A: W64 = W6 @ W4, bvc = b4 + W4a@b1 + W4b@b2
// ---------------------------------------------------------------------------
#define PA_TOT (CC * CV + CV)

__global__ void __launch_bounds__(256) prep_a_kernel(
    const float* __restrict__ W1, const float* __restrict__ b1,
    const float* __restrict__ W2, const float* __restrict__ b2,
    const float* __restrict__ W4, const float* __restrict__ b4,
    const float* __restrict__ W6)
{
    int t = blockIdx.x * blockDim.x + threadIdx.x;
    int e = t >> 2;
    int q = t & 3;
    if (e >= PA_TOT) return;
    const uint32_t qmask = 0xFu << (threadIdx.x & 28);

    float acc = 0.f;
    if (e < CC * CV) {
        int o = e / CV, j = e % CV;
        const float* w6 = W6 + o * CV;
        #pragma unroll 4
        for (int c = 72 * q; c < 72 * q + 72; c++) acc += w6[c] * W4[c * CV + j];
        acc += __shfl_xor_sync(qmask, acc, 1);
        acc += __shfl_xor_sync(qmask, acc, 2);
        if (q == 0) g_W64[e] = acc;
    } else {
        int c = e - CC * CV;
        const float* w4 = W4 + c * CV;
        if (q == 0) acc += b4[c];
        for (int j = 48 * q; j < 48 * q + 48; j++) acc += w4[j] * b1[j];
        for (int j = 24 * q; j < 24 * q + 24; j++) acc += w4[192 + j] * b2[j];
        acc += __shfl_xor_sync(qmask, acc, 1);
        acc += __shfl_xor_sync(qmask, acc, 2);
        if (q == 0) g_bvc[c] = acc;
    }
}

// ---------------------------------------------------------------------------
// Prep stage B: Wkv rows 0-95 = Wks (log2e), rows 96-191 = Wv6; bks; bv6; Wq
// ---------------------------------------------------------------------------
#define PB_O_WKS 0
#define PB_O_BKS (CC * KIN)                  // 30720
#define PB_O_WV6 (PB_O_BKS + CC)             // 30816
#define PB_O_BV6 (PB_O_WV6 + CC * KIN)       // 61536
#define PB_O_WQ  (PB_O_BV6 + CC)             // 61632
#define PB_TOT   (PB_O_WQ + CC * CC)         // 70848

__global__ void __launch_bounds__(256) prep_b_kernel(
    const float* __restrict__ W1, const float* __restrict__ b1,
    const float* __restrict__ W2, const float* __restrict__ b2,
    const float* __restrict__ W3, const float* __restrict__ b3,
    const float* __restrict__ W5, const float* __restrict__ W6)
{
    const float LOG2E = 1.44269504088896341f;
    int t = blockIdx.x * blockDim.x + threadIdx.x;
    int e = t >> 2;
    int q = t & 3;
    if (e >= PB_TOT) return;
    const uint32_t qmask = 0xFu << (threadIdx.x & 28);

    float acc = 0.f;

    if (e < PB_O_BKS) {
        int c = e / KIN, i = e % KIN;
        if (i < 128) {
            #pragma unroll 1
            for (int r = 0; r < 3; r++) {
                const float* w3 = W3 + (c + 96 * r) * 288;
                #pragma unroll 4
                for (int j = 48 * q; j < 48 * q + 48; j++) acc += w3[j] * W1[j * 128 + i];
            }
        } else {
            int ih = i - 128;
            #pragma unroll 1
            for (int r = 0; r < 3; r++) {
                const float* w3 = W3 + (c + 96 * r) * 288 + 192;
                #pragma unroll 4
                for (int j = 24 * q; j < 24 * q + 24; j++) acc += w3[j] * W2[j * 192 + ih];
            }
        }
        acc += __shfl_xor_sync(qmask, acc, 1);
        acc += __shfl_xor_sync(qmask, acc, 2);
        if (q == 0) g_Wkv[e] = __float2bfloat16(acc * LOG2E);
    } else if (e < PB_O_WV6) {
        int c = e - PB_O_BKS;
        #pragma unroll 1
        for (int r = 0; r < 3; r++) {
            int row = c + 96 * r;
            if (q == 0) acc += b3[row];
            const float* w3 = W3 + row * 288;
            for (int j = 48 * q; j < 48 * q + 48; j++) acc += w3[j] * b1[j];
            for (int j = 24 * q; j < 24 * q + 24; j++) acc += w3[192 + j] * b2[j];
        }
        acc += __shfl_xor_sync(qmask, acc, 1);
        acc += __shfl_xor_sync(qmask, acc, 2);
        if (q == 0) g_bks[c] = acc * LOG2E;
    } else if (e < PB_O_BV6) {
        int u = e - PB_O_WV6;
        int o = u / KIN, i = u % KIN;
        if (i < 128) {
            const float* w = g_W64 + o * CV;
            #pragma unroll 4
            for (int j = 48 * q; j < 48 * q + 48; j++) acc += w[j] * W1[j * 128 + i];
        } else {
            int ih = i - 128;
            const float* w = g_W64 + o * CV + 192;
            #pragma unroll 4
            for (int j = 24 * q; j < 24 * q + 24; j++) acc += w[j] * W2[j * 192 + ih];
        }
        acc += __shfl_xor_sync(qmask, acc, 1);
        acc += __shfl_xor_sync(qmask, acc, 2);
        if (q == 0) g_Wkv[CC * KIN + u] = __float2bfloat16(acc);
    } else if (e < PB_O_WQ) {
        int o = e - PB_O_BV6;
        const float* w6 = W6 + o * CV;
        #pragma unroll 4
        for (int c = 72 * q; c < 72 * q + 72; c++) acc += w6[c] * g_bvc[c];
        acc += __shfl_xor_sync(qmask, acc, 1);
        acc += __shfl_xor_sync(qmask, acc, 2);
        if (q == 0) g_bv6[o] = acc;
    } else {
        if (q == 0) {
            int u = e - PB_O_WQ;
            g_Wq[u] = __float2bfloat16(W5[u]);
        }
    }
}

// ---------------------------------------------------------------------------
// Projection GEMM. FUSED mode: M=192 (rows 0-95 -> ksum bf16 tok-major,
// rows 96-191 -> v6 fp16 ch-major). Q mode: M=96 -> q bf16 tok-major.
// ---------------------------------------------------------------------------
template<int M, int K, bool FUSED>
__device__ __forceinline__ void proj_body(
    const float* __restrict__ s0, int k0,
    const float* __restrict__ s1, int k1,
    const float* __restrict__ s2,
    const __nv_bfloat16* __restrict__ W,
    const float* __restrict__ biasA, const float* __restrict__ biasB,
    __nv_bfloat16* __restrict__ outA,   // tok-major bf16
    __half* __restrict__ outB,          // ch-major fp16 (FUSED only)
    __nv_bfloat16* sX)
{
    const int tid = threadIdx.x;
    const int warp = tid >> 5;
    const int lane = tid & 31;
    const int t4 = lane >> 2;
    const int tm4 = lane & 3;
    const int b = blockIdx.y;
    const int n0 = blockIdx.x * 64;
    const int rw = warp * 16;

    const float* p0 = s0 + (size_t)b * k0 * N_TOK;
    const float* p1 = s1 + (size_t)b * k1 * N_TOK;
    const float* p2 = s2 + (size_t)b * (K - k0 - k1) * N_TOK;

    constexpr int MT = M / 8;
    float acc[MT][4];
    #pragma unroll
    for (int i = 0; i < MT; i++) { acc[i][0]=0.f; acc[i][1]=0.f; acc[i][2]=0.f; acc[i][3]=0.f; }

    for (int kc = 0; kc < K; kc += 32) {
        #pragma unroll
        for (int it = 0; it < 16; it++) {
            int idx = it * 128 + tid;
            int k = idx >> 6;
            int n = idx & 63;
            int r = kc + k;
            float v;
            if (r < k0)            v = p0[(size_t)r * N_TOK + n0 + n];
            else if (r < k0 + k1)  v = p1[(size_t)(r - k0) * N_TOK + n0 + n];
            else                   v = p2[(size_t)(r - k0 - k1) * N_TOK + n0 + n];
            sX[n * 40 + k] = __float2bfloat16(v);
        }
        __syncthreads();

        #pragma unroll
        for (int ks = 0; ks < 2; ks++) {
            const __nv_bfloat16* qb = sX + (rw + t4) * 40 + ks * 16 + 2 * tm4;
            uint32_t a0 = ld32bf(qb);
            uint32_t a1 = ld32bf(qb + 8 * 40);
            uint32_t a2 = ld32bf(qb + 8);
            uint32_t a3 = ld32bf(qb + 8 * 40 + 8);
            #pragma unroll
            for (int mt = 0; mt < MT; mt++) {
                const __nv_bfloat16* wb = W + (size_t)(mt * 8 + t4) * K + kc + ks * 16 + 2 * tm4;
                uint32_t b0 = ld32bf(wb);
                uint32_t b1 = ld32bf(wb + 8);
                mma_bf16(acc[mt][0], acc[mt][1], acc[mt][2], acc[mt][3],
                         a0, a1, a2, a3, b0, b1);
            }
        }
        __syncthreads();
    }

    int row0 = n0 + rw + t4;
    #pragma unroll
    for (int mt = 0; mt < MT; mt++) {
        int o = mt * 8 + 2 * tm4;
        if (!FUSED || o < CC) {
            float bz0 = biasA[o], bz1 = biasA[o + 1];
            float v0 = acc[mt][0] + bz0;
            float v1 = acc[mt][1] + bz1;
            float v2 = acc[mt][2] + bz0;
            float v3 = acc[mt][3] + bz1;
            *reinterpret_cast<__nv_bfloat162*>(outA + ((size_t)(b * N_TOK + row0)) * CC + o) =
                __floats2bfloat162_rn(v0, v1);
            *reinterpret_cast<__nv_bfloat162*>(outA + ((size_t)(b * N_TOK + row0 + 8)) * CC + o) =
                __floats2bfloat162_rn(v2, v3);
        } else {
            int oc = o - CC;
            float bz0 = biasB[oc], bz1 = biasB[oc + 1];
            float v0 = acc[mt][0] + bz0;
            float v1 = acc[mt][1] + bz1;
            float v2 = acc[mt][2] + bz0;
            float v3 = acc[mt][3] + bz1;
            outB[((size_t)(b * CC + oc)) * N_TOK + row0]         = __float2half(v0);
            outB[((size_t)(b * CC + oc + 1)) * N_TOK + row0]     = __float2half(v1);
            outB[((size_t)(b * CC + oc)) * N_TOK + row0 + 8]     = __float2half(v2);
            outB[((size_t)(b * CC + oc + 1)) * N_TOK + row0 + 8] = __float2half(v3);
        }
    }
}

// Merged projection kernel: z=0 fused ksum+v6 (K=320), z=1 q (K=96).
__global__ void __launch_bounds__(128) proj_all_kernel(
    const float* __restrict__ context, const float* __restrict__ h0,
    const float* __restrict__ h1, const float* __restrict__ x,
    const __nv_bfloat16* __restrict__ Wkv,
    const float* __restrict__ bks, const float* __restrict__ bv6,
    const __nv_bfloat16* __restrict__ Wq, const float* __restrict__ b5,
    __nv_bfloat16* __restrict__ ksum_out, __half* __restrict__ v6_out,
    __nv_bfloat16* __restrict__ q_out)
{
    __shared__ __nv_bfloat16 sX[64 * 40];
    if (blockIdx.z == 0) {
        proj_body<2 * CC, KIN, true>(context, 128, h0, 96, h1, Wkv, bks, bv6,
                                     ksum_out, v6_out, sX);
    } else {
        proj_body<CC, CC, false>(x, 96, x, 0, x, Wq, b5, b5, q_out, nullptr, sX);
    }
}

// ---------------------------------------------------------------------------
// Flash attention, 16 warps (512 threads), warp-pair split.
//   Pair p (warps 2p, 2p+1) owns Q rows 16p..16p+15.
//   Warp half h: QK for K-cols 32h..32h+31 -> exp -> P(fp16) to sP[pair],
//   bar.sync(pair) [64 threads], PV over channels 48h..48h+47 using full P.
//   KV tiles 64, double-buffered cp.async. No full-CTA mid-iter syncs.
// smem (bytes): sQ[128][104]   @0       (26,624)  [reused as sm_l after loop]
//               K 2x[64][104]  @26,624  (2x13,312)
//               V6 2x[96][72]  @53,248  (2x13,824)
//               sP 8x[16][72]  @80,896  (8x2,304)  -> total 99,328
// ---------------------------------------------------------------------------
#define QT 128
#define KT 64
#define NIT (N_TOK / KT)
#define SQ_ELEMS (128 * 104)
#define SK_ELEMS (64 * 104)
#define SV_ELEMS (96 * 72)
#define SP_BOFF  80896
#define FLASH_SMEM_BYTES 99328

__global__ void __launch_bounds__(512, 1) flash_kernel(
    const __nv_bfloat16* __restrict__ qt,    // [B, N, 96]
    const __nv_bfloat16* __restrict__ kst,   // [B, N, 96] (log2e-scaled)
    const __half* __restrict__ v6,           // [B, 96, N] fp16
    const float* __restrict__ b6,
    const float* __restrict__ x,             // [B, 96, N]
    float* __restrict__ out)                 // [B, 96, N]
{
    extern __shared__ __nv_bfloat16 smem[];
    __nv_bfloat16* sQ = smem;

    const int tid = threadIdx.x;
    const int wid = tid >> 5;
    const int lane = tid & 31;
    const int t4 = lane >> 2;
    const int tm4 = lane & 3;
    const int b = blockIdx.y;
    const int n0 = blockIdx.x * QT;
    const int pair = wid >> 1;       // 0..7 -> Q rows 16*pair
    const int half = wid & 1;        // 0/1 -> K-col / channel half
    const int rw = pair * 16;

    const uint32_t smem_b = (uint32_t)__cvta_generic_to_shared(smem);
    const uint32_t sQ_b = smem_b;
    const uint32_t sK_b = smem_b + SQ_ELEMS * 2;
    const uint32_t sV_b = smem_b + (SQ_ELEMS + 2 * SK_ELEMS) * 2;
    const uint32_t sP_b = smem_b + SP_BOFF + (uint32_t)pair * 2304;
    float* sm_l = reinterpret_cast<float*>(smem);   // [2][128], post-loop reuse of sQ

    const int lg = lane >> 3;
    const int lr = lane & 7;
    const int rsel = (lg & 1) * 8 + lr;
    const int csel = (lg >> 1) * 8;
    const uint32_t aAddr0 = sQ_b + ((uint32_t)(rw + rsel) * 104 + csel) * 2;
    const uint32_t kAddr0 = sK_b + ((uint32_t)rsel * 104 + csel) * 2
                          + (uint32_t)half * 2 * (16 * 208);       // jj base
    const uint32_t vAddr0 = sV_b + ((uint32_t)rsel * 72 + csel) * 2
                          + (uint32_t)half * 3 * (16 * 144);       // channel half
    const uint32_t pAddrLd = sP_b + ((uint32_t)rsel * 72 + csel) * 2;
    const uint32_t pAddrSt = sP_b + ((uint32_t)t4 * 72 + half * 32 + 2 * tm4) * 2;

    // ---- load Q tile (1536 chunks of 8 bf16) ----
    {
        const __nv_bfloat16* qsrc = qt + ((size_t)(b * N_TOK + n0)) * 96;
        #pragma unroll
        for (int it = 0; it < 3; it++) {
            int idx = it * 512 + tid;
            int row = idx / 12;
            int c8 = idx % 12;
            *reinterpret_cast<uint4*>(sQ + row * 104 + c8 * 8) =
                *reinterpret_cast<const uint4*>(qsrc + (size_t)row * 96 + c8 * 8);
        }
    }

    // ---- async tile loader ----
    const __nv_bfloat16* kbase = kst + ((size_t)b * N_TOK) * 96;
    const __half* vbase = v6 + ((size_t)b * CC) * N_TOK;
    auto issue_tile = [&](int mt_i, int buf) {
        const int m0 = mt_i * KT;
        // K tile: 768 chunks
        #pragma unroll
        for (int it = 0; it < 2; it++) {
            int c = it * 512 + tid;
            if (c < 768) {
                int row = c / 12, col = c % 12;
                cp16(sK_b + (buf * SK_ELEMS + row * 104 + col * 8) * 2,
                     kbase + (size_t)(m0 + row) * 96 + col * 8);
            }
        }
        // V6 tile: 768 chunks
        #pragma unroll
        for (int it = 0; it < 2; it++) {
            int c = it * 512 + tid;
            if (c < 768) {
                int row = c >> 3, col = c & 7;
                cp16(sV_b + (buf * SV_ELEMS + row * 72 + col * 8) * 2,
                     vbase + (size_t)row * N_TOK + m0 + col * 8);
            }
        }
        cp_commit();
    };

    float o_[6][4];
    #pragma unroll
    for (int i = 0; i < 6; i++) { o_[i][0]=0.f; o_[i][1]=0.f; o_[i][2]=0.f; o_[i][3]=0.f; }
    float l0 = 0.f, l1 = 0.f;

    issue_tile(0, 0);

    int buf = 0;
    for (int mt_i = 0; mt_i < NIT; mt_i++) {
        cp_wait0();
        __syncthreads();
        if (mt_i + 1 < NIT) issue_tile(mt_i + 1, buf ^ 1);

        const uint32_t kB = kAddr0 + buf * (SK_ELEMS * 2);
        const uint32_t vB = vAddr0 + buf * (SV_ELEMS * 2);

        // ---- S = Q @ K^T for this half's 32 cols (bf16) ----
        float s[4][4];
        #pragma unroll
        for (int j = 0; j < 4; j++) { s[j][0]=0.f; s[j][1]=0.f; s[j][2]=0.f; s[j][3]=0.f; }
        #pragma unroll
        for (int kk = 0; kk < 6; kk++) {
            uint32_t a0, a1, a2, a3;
            ldsm4(aAddr0 + kk * 32, a0, a1, a2, a3);
            #pragma unroll
            for (int jj = 0; jj < 2; jj++) {
                uint32_t b00, b01, b10, b11;
                ldsm4(kB + jj * (16 * 208) + kk * 32, b00, b01, b10, b11);
                mma_bf16(s[2*jj][0], s[2*jj][1], s[2*jj][2], s[2*jj][3],
                         a0, a1, a2, a3, b00, b10);
                mma_bf16(s[2*jj+1][0], s[2*jj+1][1], s[2*jj+1][2], s[2*jj+1][3],
                         a0, a1, a2, a3, b01, b11);
            }
        }

        // ---- P = exp2(S); partial row sums; store fp16 P to sP ----
        #pragma unroll
        for (int j = 0; j < 4; j++) {
            uint32_t e01 = ex2_f16x2(s[j][0], s[j][1]);
            uint32_t e23 = ex2_f16x2(s[j][2], s[j][3]);
            float2 f01 = __half22float2(*reinterpret_cast<__half2*>(&e01));
            float2 f23 = __half22float2(*reinterpret_cast<__half2*>(&e23));
            l0 += f01.x + f01.y;
            l1 += f23.x + f23.y;
            sts32(pAddrSt + (uint32_t)j * 16, e01);
            sts32(pAddrSt + (uint32_t)(8 * 72 * 2) + (uint32_t)j * 16, e23);
        }
        bar_pair(pair + 1);   // pair's P complete

        // ---- P A-fragments via ldsm (full 64-k) ----
        uint32_t pa[4][4];
        #pragma unroll
        for (int g = 0; g < 4; g++)
            ldsm4(pAddrLd + g * 32, pa[g][0], pa[g][1], pa[g][2], pa[g][3]);

        // ---- O += P @ V6^T over this half's 48 channels (fp16) ----
        #pragma unroll
        for (int g = 0; g < 4; g++) {
            #pragma unroll
            for (int cc = 0; cc < 3; cc++) {
                uint32_t r0, r1, r2, r3;
                ldsm4(vB + cc * (16 * 144) + g * 32, r0, r1, r2, r3);
                mma_f16(o_[2*cc][0], o_[2*cc][1], o_[2*cc][2], o_[2*cc][3],
                        pa[g][0], pa[g][1], pa[g][2], pa[g][3], r0, r2);
                mma_f16(o_[2*cc+1][0], o_[2*cc+1][1], o_[2*cc+1][2], o_[2*cc+1][3],
                        pa[g][0], pa[g][1], pa[g][2], pa[g][3], r1, r3);
            }
        }
        buf ^= 1;
        __syncthreads();   // protects sP overwrite + K/V buf reuse
    }

    // ---- partial row sums -> sm_l[half][row] ----
    l0 += __shfl_xor_sync(0xffffffffu, l0, 1);
    l0 += __shfl_xor_sync(0xffffffffu, l0, 2);
    l1 += __shfl_xor_sync(0xffffffffu, l1, 1);
    l1 += __shfl_xor_sync(0xffffffffu, l1, 2);
    if (tm4 == 0) {
        sm_l[half * 128 + rw + t4] = l0;
        sm_l[half * 128 + rw + t4 + 8] = l1;
    }
    __syncthreads();

    // ---- epilogue: out = O/l + b6 + x ----
    const int r0i = rw + t4;
    const float inv0 = 1.f / (sm_l[r0i] + sm_l[128 + r0i]);
    const float inv1 = 1.f / (sm_l[r0i + 8] + sm_l[128 + r0i + 8]);

    int n = n0 + r0i;
    #pragma unroll
    for (int mt = 0; mt < 6; mt++) {
        int o = half * 48 + mt * 8 + 2 * tm4;
        size_t i00 = ((size_t)(b * CC + o)) * N_TOK + n;
        size_t i01 = i00 + N_TOK;
        out[i00]     = o_[mt][0] * inv0 + b6[o]     + x[i00];
        out[i01]     = o_[mt][1] * inv0 + b6[o + 1] + x[i01];
        out[i00 + 8] = o_[mt][2] * inv1 + b6[o]     + x[i00 + 8];
        out[i01 + 8] = o_[mt][3] * inv1 + b6[o + 1] + x[i01 + 8];
    }
}

// ---------------------------------------------------------------------------
// Launch
// ---------------------------------------------------------------------------
extern "C" void kernel_launch(void* const* d_in, const int* in_sizes, int n_in,
                              void* d_out, int out_size)
{
    const float* context = (const float*)d_in[0];
    const float* h0 = (const float*)d_in[1];
    const float* h1 = (const float*)d_in[2];
    const float* x  = (const float*)d_in[3];
    const float* W1 = (const float*)d_in[4];
    const float* b1 = (const float*)d_in[5];
    const float* W2 = (const float*)d_in[6];
    const float* b2 = (const float*)d_in[7];
    const float* W3 = (const float*)d_in[8];
    const float* b3 = (const float*)d_in[9];
    const float* W4 = (const float*)d_in[10];
    const float* b4 = (const float*)d_in[11];
    const float* W5 = (const float*)d_in[12];
    const float* b5 = (const float*)d_in[13];
    const float* W6 = (const float*)d_in[14];
    const float* b6 = (const float*)d_in[15];
    float* out = (float*)d_out;

    void *pWkv, *pBks, *pBv6, *pWq, *pKsum, *pQ, *pV6;
    cudaGetSymbolAddress(&pWkv, g_Wkv);
    cudaGetSymbolAddress(&pBks, g_bks);
    cudaGetSymbolAddress(&pBv6, g_bv6);
    cudaGetSymbolAddress(&pWq, g_Wq);
    cudaGetSymbolAddress(&pKsum, g_ksum);
    cudaGetSymbolAddress(&pQ, g_q);
    cudaGetSymbolAddress(&pV6, g_v6);

    cudaFuncSetAttribute(flash_kernel, cudaFuncAttributeMaxDynamicSharedMemorySize,
                         FLASH_SMEM_BYTES);

    prep_a_kernel<<<(PA_TOT * 4 + 255) / 256, 256>>>(W1, b1, W2, b2, W4, b4, W6);
    prep_b_kernel<<<(PB_TOT * 4 + 255) / 256, 256>>>(W1, b1, W2, b2, W3, b3, W5, W6);

    dim3 pgrid(N_TOK / 64, BATCH, 2);
    proj_all_kernel<<<pgrid, 128>>>(
        context, h0, h1, x,
        (const __nv_bfloat16*)pWkv, (const float*)pBks, (const float*)pBv6,
        (const __nv_bfloat16*)pWq, b5,
        (__nv_bfloat16*)pKsum, (__half*)pV6, (__nv_bfloat16*)pQ);

    dim3 fgrid(N_TOK / QT, BATCH);
    flash_kernel<<<fgrid, 512, FLASH_SMEM_BYTES>>>(
        (const __nv_bfloat16*)pQ, (const __nv_bfloat16*)pKsum,
        (const __half*)pV6, b6, x, out);
}

// round 15
// speedup vs baseline: 1.0500x; 1.0500x over previous
#include <cuda_runtime.h>
#include <cuda_bf16.h>
#include <cuda_fp16.h>
#include <cstdint>

// Problem constants (fixed shapes)
#define N_TOK 8192     // D*H*W
#define BATCH 2
#define CC 96
#define CV 288
#define KIN 320

// ---------------------------------------------------------------------------
// Device scratch
// ---------------------------------------------------------------------------
__device__ float g_W64[CC * CV];     // W6 @ W4  (fp32, stage-A scratch)
__device__ float g_bvc[CV];          // combined v bias (fp32, stage-A scratch)

__device__ __align__(128) __nv_bfloat16 g_Wkv[2 * CC * KIN]; // rows 0-95: Wks(log2e), 96-191: Wv6
__device__ float         g_bks[CC];
__device__ float         g_bv6[CC];
__device__ __align__(128) __nv_bfloat16 g_Wq[CC * CC];
__device__ __align__(128) __nv_bfloat16 g_ksum[(size_t)BATCH * N_TOK * CC];  // [B,N,96] bf16 (log2e)
__device__ __align__(128) __nv_bfloat16 g_q[(size_t)BATCH * N_TOK * CC];     // [B,N,96] bf16
__device__ __align__(128) __half        g_v6[(size_t)BATCH * CC * N_TOK];    // [B,96,N] fp16

// ---------------------------------------------------------------------------
// Helpers
// ---------------------------------------------------------------------------
__device__ __forceinline__ uint32_t ld32bf(const __nv_bfloat16* p) {
    return *reinterpret_cast<const uint32_t*>(p);
}

__device__ __forceinline__ void mma_bf16(float& d0, float& d1, float& d2, float& d3,
                                         uint32_t a0, uint32_t a1, uint32_t a2, uint32_t a3,
                                         uint32_t b0, uint32_t b1)
{
    asm volatile(
        "mma.sync.aligned.m16n8k16.row.col.f32.bf16.bf16.f32 "
        "{%0,%1,%2,%3}, {%4,%5,%6,%7}, {%8,%9}, {%0,%1,%2,%3};\n"
        : "+f"(d0), "+f"(d1), "+f"(d2), "+f"(d3)
        : "r"(a0), "r"(a1), "r"(a2), "r"(a3), "r"(b0), "r"(b1));
}

__device__ __forceinline__ void mma_f16(float& d0, float& d1, float& d2, float& d3,
                                        uint32_t a0, uint32_t a1, uint32_t a2, uint32_t a3,
                                        uint32_t b0, uint32_t b1)
{
    asm volatile(
        "mma.sync.aligned.m16n8k16.row.col.f32.f16.f16.f32 "
        "{%0,%1,%2,%3}, {%4,%5,%6,%7}, {%8,%9}, {%0,%1,%2,%3};\n"
        : "+f"(d0), "+f"(d1), "+f"(d2), "+f"(d3)
        : "r"(a0), "r"(a1), "r"(a2), "r"(a3), "r"(b0), "r"(b1));
}

__device__ __forceinline__ void ldsm4(uint32_t addr, uint32_t& r0, uint32_t& r1,
                                      uint32_t& r2, uint32_t& r3)
{
    asm volatile("ldmatrix.sync.aligned.m8n8.x4.shared.b16 {%0,%1,%2,%3}, [%4];\n"
                 : "=r"(r0), "=r"(r1), "=r"(r2), "=r"(r3) : "r"(addr));
}

__device__ __forceinline__ void cp16(uint32_t smem_dst, const void* gsrc)
{
    asm volatile("cp.async.cg.shared.global [%0], [%1], 16;\n"
                 :: "r"(smem_dst), "l"(gsrc));
}
__device__ __forceinline__ void cp_commit() { asm volatile("cp.async.commit_group;\n"); }
template<int N> __device__ __forceinline__ void cp_waitN()
{
    asm volatile("cp.async.wait_group %0;\n" :: "n"(N));
}

// exp2 on two packed fp16; inputs fp32 (log2 domain), output f16x2 bits
__device__ __forceinline__ uint32_t ex2_f16x2(float a, float b)
{
    __half2 h = __floats2half2_rn(a, b);
    uint32_t hin = *reinterpret_cast<uint32_t*>(&h);
    uint32_t r;
    asm("ex2.approx.f16x2 %0, %1;" : "=r"(r) : "r"(hin));
    return r;
}

// ---------------------------------------------------------------------------
// Prep stage A: W64 = W6 @ W4, bvc = b4 + W4a@b1 + W4b@b2
// ---------------------------------------------------------------------------
#define PA_TOT (CC * CV + CV)

__global__ void __launch_bounds__(256) prep_a_kernel(
    const float* __restrict__ W1, const float* __restrict__ b1,
    const float* __restrict__ W2, const float* __restrict__ b2,
    const float* __restrict__ W4, const float* __restrict__ b4,
    const float* __restrict__ W6)
{
    int t = blockIdx.x * blockDim.x + threadIdx.x;
    int e = t >> 2;
    int q = t & 3;
    if (e >= PA_TOT) return;
    const uint32_t qmask = 0xFu << (threadIdx.x & 28);

    float acc = 0.f;
    if (e < CC * CV) {
        int o = e / CV, j = e % CV;
        const float* w6 = W6 + o * CV;
        #pragma unroll 4
        for (int c = 72 * q; c < 72 * q + 72; c++) acc += w6[c] * W4[c * CV + j];
        acc += __shfl_xor_sync(qmask, acc, 1);
        acc += __shfl_xor_sync(qmask, acc, 2);
        if (q == 0) g_W64[e] = acc;
    } else {
        int c = e - CC * CV;
        const float* w4 = W4 + c * CV;
        if (q == 0) acc += b4[c];
        for (int j = 48 * q; j < 48 * q + 48; j++) acc += w4[j] * b1[j];
        for (int j = 24 * q; j < 24 * q + 24; j++) acc += w4[192 + j] * b2[j];
        acc += __shfl_xor_sync(qmask, acc, 1);
        acc += __shfl_xor_sync(qmask, acc, 2);
        if (q == 0) g_bvc[c] = acc;
    }
}

// ---------------------------------------------------------------------------
// Prep stage B: Wkv rows 0-95 = Wks (log2e), rows 96-191 = Wv6; bks; bv6; Wq
// ---------------------------------------------------------------------------
#define PB_O_WKS 0
#define PB_O_BKS (CC * KIN)                  // 30720
#define PB_O_WV6 (PB_O_BKS + CC)             // 30816
#define PB_O_BV6 (PB_O_WV6 + CC * KIN)       // 61536
#define PB_O_WQ  (PB_O_BV6 + CC)             // 61632
#define PB_TOT   (PB_O_WQ + CC * CC)         // 70848

__global__ void __launch_bounds__(256) prep_b_kernel(
    const float* __restrict__ W1, const float* __restrict__ b1,
    const float* __restrict__ W2, const float* __restrict__ b2,
    const float* __restrict__ W3, const float* __restrict__ b3,
    const float* __restrict__ W5, const float* __restrict__ W6)
{
    const float LOG2E = 1.44269504088896341f;
    int t = blockIdx.x * blockDim.x + threadIdx.x;
    int e = t >> 2;
    int q = t & 3;
    if (e >= PB_TOT) return;
    const uint32_t qmask = 0xFu << (threadIdx.x & 28);

    float acc = 0.f;

    if (e < PB_O_BKS) {
        int c = e / KIN, i = e % KIN;
        if (i < 128) {
            #pragma unroll 1
            for (int r = 0; r < 3; r++) {
                const float* w3 = W3 + (c + 96 * r) * 288;
                #pragma unroll 4
                for (int j = 48 * q; j < 48 * q + 48; j++) acc += w3[j] * W1[j * 128 + i];
            }
        } else {
            int ih = i - 128;
            #pragma unroll 1
            for (int r = 0; r < 3; r++) {
                const float* w3 = W3 + (c + 96 * r) * 288 + 192;
                #pragma unroll 4
                for (int j = 24 * q; j < 24 * q + 24; j++) acc += w3[j] * W2[j * 192 + ih];
            }
        }
        acc += __shfl_xor_sync(qmask, acc, 1);
        acc += __shfl_xor_sync(qmask, acc, 2);
        if (q == 0) g_Wkv[e] = __float2bfloat16(acc * LOG2E);
    } else if (e < PB_O_WV6) {
        int c = e - PB_O_BKS;
        #pragma unroll 1
        for (int r = 0; r < 3; r++) {
            int row = c + 96 * r;
            if (q == 0) acc += b3[row];
            const float* w3 = W3 + row * 288;
            for (int j = 48 * q; j < 48 * q + 48; j++) acc += w3[j] * b1[j];
            for (int j = 24 * q; j < 24 * q + 24; j++) acc += w3[192 + j] * b2[j];
        }
        acc += __shfl_xor_sync(qmask, acc, 1);
        acc += __shfl_xor_sync(qmask, acc, 2);
        if (q == 0) g_bks[c] = acc * LOG2E;
    } else if (e < PB_O_BV6) {
        int u = e - PB_O_WV6;
        int o = u / KIN, i = u % KIN;
        if (i < 128) {
            const float* w = g_W64 + o * CV;
            #pragma unroll 4
            for (int j = 48 * q; j < 48 * q + 48; j++) acc += w[j] * W1[j * 128 + i];
        } else {
            int ih = i - 128;
            const float* w = g_W64 + o * CV + 192;
            #pragma unroll 4
            for (int j = 24 * q; j < 24 * q + 24; j++) acc += w[j] * W2[j * 192 + ih];
        }
        acc += __shfl_xor_sync(qmask, acc, 1);
        acc += __shfl_xor_sync(qmask, acc, 2);
        if (q == 0) g_Wkv[CC * KIN + u] = __float2bfloat16(acc);
    } else if (e < PB_O_WQ) {
        int o = e - PB_O_BV6;
        const float* w6 = W6 + o * CV;
        #pragma unroll 4
        for (int c = 72 * q; c < 72 * q + 72; c++) acc += w6[c] * g_bvc[c];
        acc += __shfl_xor_sync(qmask, acc, 1);
        acc += __shfl_xor_sync(qmask, acc, 2);
        if (q == 0) g_bv6[o] = acc;
    } else {
        if (q == 0) {
            int u = e - PB_O_WQ;
            g_Wq[u] = __float2bfloat16(W5[u]);
        }
    }
}

// ---------------------------------------------------------------------------
// Projection GEMM. FUSED mode: M=192 (rows 0-95 -> ksum bf16 tok-major,
// rows 96-191 -> v6 fp16 ch-major). Q mode: M=96 -> q bf16 tok-major.
// ---------------------------------------------------------------------------
template<int M, int K, bool FUSED>
__device__ __forceinline__ void proj_body(
    const float* __restrict__ s0, int k0,
    const float* __restrict__ s1, int k1,
    const float* __restrict__ s2,
    const __nv_bfloat16* __restrict__ W,
    const float* __restrict__ biasA, const float* __restrict__ biasB,
    __nv_bfloat16* __restrict__ outA,   // tok-major bf16
    __half* __restrict__ outB,          // ch-major fp16 (FUSED only)
    __nv_bfloat16* sX)
{
    const int tid = threadIdx.x;
    const int warp = tid >> 5;
    const int lane = tid & 31;
    const int t4 = lane >> 2;
    const int tm4 = lane & 3;
    const int b = blockIdx.y;
    const int n0 = blockIdx.x * 64;
    const int rw = warp * 16;

    const float* p0 = s0 + (size_t)b * k0 * N_TOK;
    const float* p1 = s1 + (size_t)b * k1 * N_TOK;
    const float* p2 = s2 + (size_t)b * (K - k0 - k1) * N_TOK;

    constexpr int MT = M / 8;
    float acc[MT][4];
    #pragma unroll
    for (int i = 0; i < MT; i++) { acc[i][0]=0.f; acc[i][1]=0.f; acc[i][2]=0.f; acc[i][3]=0.f; }

    for (int kc = 0; kc < K; kc += 32) {
        #pragma unroll
        for (int it = 0; it < 16; it++) {
            int idx = it * 128 + tid;
            int k = idx >> 6;
            int n = idx & 63;
            int r = kc + k;
            float v;
            if (r < k0)            v = p0[(size_t)r * N_TOK + n0 + n];
            else if (r < k0 + k1)  v = p1[(size_t)(r - k0) * N_TOK + n0 + n];
            else                   v = p2[(size_t)(r - k0 - k1) * N_TOK + n0 + n];
            sX[n * 40 + k] = __float2bfloat16(v);
        }
        __syncthreads();

        #pragma unroll
        for (int ks = 0; ks < 2; ks++) {
            const __nv_bfloat16* qb = sX + (rw + t4) * 40 + ks * 16 + 2 * tm4;
            uint32_t a0 = ld32bf(qb);
            uint32_t a1 = ld32bf(qb + 8 * 40);
            uint32_t a2 = ld32bf(qb + 8);
            uint32_t a3 = ld32bf(qb + 8 * 40 + 8);
            #pragma unroll
            for (int mt = 0; mt < MT; mt++) {
                const __nv_bfloat16* wb = W + (size_t)(mt * 8 + t4) * K + kc + ks * 16 + 2 * tm4;
                uint32_t b0 = ld32bf(wb);
                uint32_t b1 = ld32bf(wb + 8);
                mma_bf16(acc[mt][0], acc[mt][1], acc[mt][2], acc[mt][3],
                         a0, a1, a2, a3, b0, b1);
            }
        }
        __syncthreads();
    }

    int row0 = n0 + rw + t4;
    #pragma unroll
    for (int mt = 0; mt < MT; mt++) {
        int o = mt * 8 + 2 * tm4;
        if (!FUSED || o < CC) {
            float bz0 = biasA[o], bz1 = biasA[o + 1];
            float v0 = acc[mt][0] + bz0;
            float v1 = acc[mt][1] + bz1;
            float v2 = acc[mt][2] + bz0;
            float v3 = acc[mt][3] + bz1;
            *reinterpret_cast<__nv_bfloat162*>(outA + ((size_t)(b * N_TOK + row0)) * CC + o) =
                __floats2bfloat162_rn(v0, v1);
            *reinterpret_cast<__nv_bfloat162*>(outA + ((size_t)(b * N_TOK + row0 + 8)) * CC + o) =
                __floats2bfloat162_rn(v2, v3);
        } else {
            int oc = o - CC;
            float bz0 = biasB[oc], bz1 = biasB[oc + 1];
            float v0 = acc[mt][0] + bz0;
            float v1 = acc[mt][1] + bz1;
            float v2 = acc[mt][2] + bz0;
            float v3 = acc[mt][3] + bz1;
            outB[((size_t)(b * CC + oc)) * N_TOK + row0]         = __float2half(v0);
            outB[((size_t)(b * CC + oc + 1)) * N_TOK + row0]     = __float2half(v1);
            outB[((size_t)(b * CC + oc)) * N_TOK + row0 + 8]     = __float2half(v2);
            outB[((size_t)(b * CC + oc + 1)) * N_TOK + row0 + 8] = __float2half(v3);
        }
    }
}

// Merged projection kernel: z=0 fused ksum+v6 (K=320), z=1 q (K=96).
__global__ void __launch_bounds__(128) proj_all_kernel(
    const float* __restrict__ context, const float* __restrict__ h0,
    const float* __restrict__ h1, const float* __restrict__ x,
    const __nv_bfloat16* __restrict__ Wkv,
    const float* __restrict__ bks, const float* __restrict__ bv6,
    const __nv_bfloat16* __restrict__ Wq, const float* __restrict__ b5,
    __nv_bfloat16* __restrict__ ksum_out, __half* __restrict__ v6_out,
    __nv_bfloat16* __restrict__ q_out)
{
    __shared__ __nv_bfloat16 sX[64 * 40];
    if (blockIdx.z == 0) {
        proj_body<2 * CC, KIN, true>(context, 128, h0, 96, h1, Wkv, bks, bv6,
                                     ksum_out, v6_out, sX);
    } else {
        proj_body<CC, CC, false>(x, 96, x, 0, x, Wq, b5, b5, q_out, nullptr, sX);
    }
}

// ---------------------------------------------------------------------------
// Flash attention, software-pipelined (8 warps, 256 threads).
//   Per iter: exp_i -> wait tile i+1 + ONE barrier -> QK_{i+1} ->
//             issue tile i+2 -> PV_i.   Q A-frags preloaded in registers.
//   K double-buffered, V6 triple-buffered (so tile i+2 never collides with
//   PV_i's reads). One __syncthreads per iteration.
// smem (bytes): sQ[128][104] @0 (26,624) | K 2x[64][104] @26,624 (2x13,312)
//               V6 3x[96][72] @53,248 (3x13,824) -> total 94,720
// ---------------------------------------------------------------------------
#define QT 128
#define KT 64
#define NIT (N_TOK / KT)
#define SQ_ELEMS (128 * 104)
#define SK_ELEMS (64 * 104)
#define SV_ELEMS (96 * 72)
#define SK_OFF (SQ_ELEMS * 2)
#define SV_OFF (SK_OFF + 2 * SK_ELEMS * 2)
#define K_BUF  (SK_ELEMS * 2)
#define V_BUF  (SV_ELEMS * 2)
#define FLASH_SMEM_BYTES (SV_OFF + 3 * V_BUF)   // 94,720

__global__ void __launch_bounds__(256, 1) flash_kernel(
    const __nv_bfloat16* __restrict__ qt,    // [B, N, 96]
    const __nv_bfloat16* __restrict__ kst,   // [B, N, 96] (log2e-scaled)
    const __half* __restrict__ v6,           // [B, 96, N] fp16
    const float* __restrict__ b6,
    const float* __restrict__ x,             // [B, 96, N]
    float* __restrict__ out)                 // [B, 96, N]
{
    extern __shared__ __nv_bfloat16 smem[];
    __nv_bfloat16* sQ = smem;

    const int tid = threadIdx.x;
    const int warp = tid >> 5;
    const int lane = tid & 31;
    const int t4 = lane >> 2;
    const int tm4 = lane & 3;
    const int b = blockIdx.y;
    const int n0 = blockIdx.x * QT;
    const int rw = warp * 16;

    const uint32_t smem_b = (uint32_t)__cvta_generic_to_shared(smem);
    const uint32_t sQ_b = smem_b;
    const uint32_t sK_b = smem_b + SK_OFF;
    const uint32_t sV_b = smem_b + SV_OFF;

    const int lg = lane >> 3;
    const int lr = lane & 7;
    const int rsel = (lg & 1) * 8 + lr;
    const int csel = (lg >> 1) * 8;
    const uint32_t aAddr0 = sQ_b + ((rw + rsel) * 104 + csel) * 2;
    const uint32_t kAddr0 = sK_b + (rsel * 104 + csel) * 2;
    const uint32_t vAddr0 = sV_b + (rsel * 72 + csel) * 2;

    // ---- load Q tile, then hoist A-fragments to registers ----
    {
        const __nv_bfloat16* qsrc = qt + ((size_t)(b * N_TOK + n0)) * 96;
        #pragma unroll
        for (int it = 0; it < 6; it++) {
            int idx = it * 256 + tid;
            int row = idx / 12;
            int c8 = idx % 12;
            *reinterpret_cast<uint4*>(sQ + row * 104 + c8 * 8) =
                *reinterpret_cast<const uint4*>(qsrc + (size_t)row * 96 + c8 * 8);
        }
    }
    __syncthreads();
    uint32_t qa[6][4];
    #pragma unroll
    for (int kk = 0; kk < 6; kk++)
        ldsm4(aAddr0 + kk * 32, qa[kk][0], qa[kk][1], qa[kk][2], qa[kk][3]);

    // ---- async tile loader: tile t -> K buf t&1, V buf t%3 ----
    const __nv_bfloat16* kbase = kst + ((size_t)b * N_TOK) * 96;
    const __half* vbase = v6 + ((size_t)b * CC) * N_TOK;
    auto issue_tile = [&](int t) {
        const int m0 = t * KT;
        const uint32_t kd = sK_b + (uint32_t)(t & 1) * K_BUF;
        const uint32_t vd = sV_b + (uint32_t)(t % 3) * V_BUF;
        // K tile: 64 rows x 96 cols = 768 16B chunks
        #pragma unroll
        for (int it = 0; it < 3; it++) {
            int c = it * 256 + tid;
            int row = c / 12, col = c % 12;
            cp16(kd + ((uint32_t)row * 104 + col * 8) * 2,
                 kbase + (size_t)(m0 + row) * 96 + col * 8);
        }
        // V6 tile: 96 rows x 64 cols = 768 16B chunks
        #pragma unroll
        for (int it = 0; it < 3; it++) {
            int c = it * 256 + tid;
            int row = c >> 3, col = c & 7;
            cp16(vd + ((uint32_t)row * 72 + col * 8) * 2,
                 vbase + (size_t)row * N_TOK + m0 + col * 8);
        }
        cp_commit();
    };

    // ---- QK for one K buffer ----
    auto qk = [&](float s[8][4], uint32_t kB) {
        #pragma unroll
        for (int j = 0; j < 8; j++) { s[j][0]=0.f; s[j][1]=0.f; s[j][2]=0.f; s[j][3]=0.f; }
        #pragma unroll
        for (int kk = 0; kk < 6; kk++) {
            #pragma unroll
            for (int jj = 0; jj < 4; jj++) {
                uint32_t b00, b01, b10, b11;
                ldsm4(kB + jj * (16 * 208) + kk * 32, b00, b01, b10, b11);
                mma_bf16(s[2*jj][0], s[2*jj][1], s[2*jj][2], s[2*jj][3],
                         qa[kk][0], qa[kk][1], qa[kk][2], qa[kk][3], b00, b10);
                mma_bf16(s[2*jj+1][0], s[2*jj+1][1], s[2*jj+1][2], s[2*jj+1][3],
                         qa[kk][0], qa[kk][1], qa[kk][2], qa[kk][3], b01, b11);
            }
        }
    };

    float o_[12][4];
    #pragma unroll
    for (int i = 0; i < 12; i++) { o_[i][0]=0.f; o_[i][1]=0.f; o_[i][2]=0.f; o_[i][3]=0.f; }
    float l0 = 0.f, l1 = 0.f;

    issue_tile(0);
    issue_tile(1);
    cp_waitN<1>();          // tile 0 complete
    __syncthreads();

    float s[8][4];
    qk(s, kAddr0);          // S for tile 0 (K buf 0)

    for (int i = 0; i < NIT; i++) {
        // ---- exp_i: P = exp2(S), row sums, pack fp16 A-frags ----
        uint32_t pa[4][4];
        #pragma unroll
        for (int j = 0; j < 8; j++) {
            uint32_t e01 = ex2_f16x2(s[j][0], s[j][1]);
            uint32_t e23 = ex2_f16x2(s[j][2], s[j][3]);
            float2 f01 = __half22float2(*reinterpret_cast<__half2*>(&e01));
            float2 f23 = __half22float2(*reinterpret_cast<__half2*>(&e23));
            l0 += f01.x + f01.y;
            l1 += f23.x + f23.y;
            pa[j >> 1][(j & 1) * 2]     = e01;
            pa[j >> 1][(j & 1) * 2 + 1] = e23;
        }

        // ---- wait tile i+1, single barrier, then QK_{i+1} ----
        if (i + 1 < NIT) {
            cp_waitN<0>();
            __syncthreads();     // tile i+1 visible; all warps done QK_i & PV_{i-1}
            qk(s, kAddr0 + (uint32_t)((i + 1) & 1) * K_BUF);
            if (i + 2 < NIT) issue_tile(i + 2);
        }

        // ---- PV_i: O += P @ V6^T (V buf i%3) ----
        const uint32_t vB = vAddr0 + (uint32_t)(i % 3) * V_BUF;
        #pragma unroll
        for (int g = 0; g < 4; g++) {
            #pragma unroll
            for (int cc = 0; cc < 6; cc++) {
                uint32_t r0, r1, r2, r3;
                ldsm4(vB + cc * (16 * 144) + g * 32, r0, r1, r2, r3);
                mma_f16(o_[2*cc][0], o_[2*cc][1], o_[2*cc][2], o_[2*cc][3],
                        pa[g][0], pa[g][1], pa[g][2], pa[g][3], r0, r2);
                mma_f16(o_[2*cc+1][0], o_[2*cc+1][1], o_[2*cc+1][2], o_[2*cc+1][3],
                        pa[g][0], pa[g][1], pa[g][2], pa[g][3], r1, r3);
            }
        }
    }

    // ---- finalize softmax normalization (in-warp, rows owned by warp) ----
    l0 += __shfl_xor_sync(0xffffffffu, l0, 1);
    l0 += __shfl_xor_sync(0xffffffffu, l0, 2);
    l1 += __shfl_xor_sync(0xffffffffu, l1, 1);
    l1 += __shfl_xor_sync(0xffffffffu, l1, 2);
    float inv0 = 1.f / l0;
    float inv1 = 1.f / l1;

    // ---- epilogue: out = O/l + b6 + x (W6 folded into V6) ----
    int n = n0 + rw + t4;
    #pragma unroll
    for (int mt = 0; mt < 12; mt++) {
        int o = mt * 8 + 2 * tm4;
        size_t i00 = ((size_t)(b * CC + o)) * N_TOK + n;
        size_t i01 = i00 + N_TOK;
        out[i00]     = o_[mt][0] * inv0 + b6[o]     + x[i00];
        out[i01]     = o_[mt][1] * inv0 + b6[o + 1] + x[i01];
        out[i00 + 8] = o_[mt][2] * inv1 + b6[o]     + x[i00 + 8];
        out[i01 + 8] = o_[mt][3] * inv1 + b6[o + 1] + x[i01 + 8];
    }
}

// ---------------------------------------------------------------------------
// Launch
// ---------------------------------------------------------------------------
extern "C" void kernel_launch(void* const* d_in, const int* in_sizes, int n_in,
                              void* d_out, int out_size)
{
    const float* context = (const float*)d_in[0];
    const float* h0 = (const float*)d_in[1];
    const float* h1 = (const float*)d_in[2];
    const float* x  = (const float*)d_in[3];
    const float* W1 = (const float*)d_in[4];
    const float* b1 = (const float*)d_in[5];
    const float* W2 = (const float*)d_in[6];
    const float* b2 = (const float*)d_in[7];
    const float* W3 = (const float*)d_in[8];
    const float* b3 = (const float*)d_in[9];
    const float* W4 = (const float*)d_in[10];
    const float* b4 = (const float*)d_in[11];
    const float* W5 = (const float*)d_in[12];
    const float* b5 = (const float*)d_in[13];
    const float* W6 = (const float*)d_in[14];
    const float* b6 = (const float*)d_in[15];
    float* out = (float*)d_out;

    void *pWkv, *pBks, *pBv6, *pWq, *pKsum, *pQ, *pV6;
    cudaGetSymbolAddress(&pWkv, g_Wkv);
    cudaGetSymbolAddress(&pBks, g_bks);
    cudaGetSymbolAddress(&pBv6, g_bv6);
    cudaGetSymbolAddress(&pWq, g_Wq);
    cudaGetSymbolAddress(&pKsum, g_ksum);
    cudaGetSymbolAddress(&pQ, g_q);
    cudaGetSymbolAddress(&pV6, g_v6);

    cudaFuncSetAttribute(flash_kernel, cudaFuncAttributeMaxDynamicSharedMemorySize,
                         FLASH_SMEM_BYTES);

    prep_a_kernel<<<(PA_TOT * 4 + 255) / 256, 256>>>(W1, b1, W2, b2, W4, b4, W6);
    prep_b_kernel<<<(PB_TOT * 4 + 255) / 256, 256>>>(W1, b1, W2, b2, W3, b3, W5, W6);

    dim3 pgrid(N_TOK / 64, BATCH, 2);
    proj_all_kernel<<<pgrid, 128>>>(
        context, h0, h1, x,
        (const __nv_bfloat16*)pWkv, (const float*)pBks, (const float*)pBv6,
        (const __nv_bfloat16*)pWq, b5,
        (__nv_bfloat16*)pKsum, (__half*)pV6, (__nv_bfloat16*)pQ);

    dim3 fgrid(N_TOK / QT, BATCH);
    flash_kernel<<<fgrid, 256, FLASH_SMEM_BYTES>>>(
        (const __nv_bfloat16*)pQ, (const __nv_bfloat16*)pKsum,
        (const __half*)pV6, b6, x, out);
}